// round 14
// baseline (speedup 1.0000x reference)
#include <cuda_runtime.h>
#include <cuda_fp16.h>
#include <math.h>

#define N_ENT 100000
#define N_USR 50000
#define N_TOT 150000
#define DIM 64
#define E_KG 1500000
#define E_CF 1500000
#define LEAKY 0.01f

#define NB_KG 98    // ceil(100000/1024)
#define NB_AIN 147  // ceil(150000/1024)
#define NBF 1563    // ceil(100000/64)

#define B_H 11719   // ceil(3,000,000/256) edge hist
#define B_I 9375    // N_TOT*16/256 init float4
#define B_P 9       // PQ + cr
#define B_S 2       // spine zero
#define B_ATBT 1563

// ---------------- scratch (static device globals; zero-initialized at load) ----------------
__device__ float d_PQ[128 * 16];
__device__ float d_cr[16];
__device__ float d_At[(size_t)N_ENT * 16];
__device__ float d_Bt[(size_t)N_ENT * 16];
__device__ int   d_kg_cnt[N_ENT];
__device__ int   d_kg_rp[N_ENT + 1];
__device__ int2  d_csr_kg[E_KG];            // (tail*128 byte-offset, half2(a,a) bits)
__device__ int   d_ain_cnt[N_TOT];
__device__ int   d_ain_rp[N_TOT + 1];
__device__ int2  d_csr_ain[E_CF];           // (col*128 byte-offset, half2(v,v) bits)
__device__ unsigned d_spine[512];
__device__ __align__(16) __half2 d_kg16[2][(size_t)N_ENT * 32];  // fp16 gather source (kg)
__device__ __align__(16) __half2 d_xy16[2][(size_t)N_TOT * 32];  // fp16 gather source (ain)
__device__ float d_ig[(size_t)N_TOT * DIM];                      // fp32 ain-spmm out
__device__ float d_sum[(size_t)N_TOT * DIM];

// ---------------- helpers ----------------
__device__ __forceinline__ void fma2(unsigned long long& d, unsigned long long a,
                                     unsigned long long b) {
    asm("fma.rn.f32x2 %0, %1, %2, %0;" : "+l"(d) : "l"(a), "l"(b));
}
__device__ __forceinline__ unsigned long long splat2(float x) {
    unsigned long long r;
    asm("mov.b64 %0, {%1, %1};" : "=l"(r) : "r"(__float_as_uint(x)));
    return r;
}
__device__ __forceinline__ void unpack2(unsigned long long v, float& lo, float& hi) {
    unsigned a, b;
    asm("mov.b64 {%0, %1}, %2;" : "=r"(a), "=r"(b) : "l"(v));
    lo = __uint_as_float(a);
    hi = __uint_as_float(b);
}
__device__ __forceinline__ uint2 pack_h4(float a, float b, float c, float d) {
    __half2 h0 = __floats2half2_rn(a, b);
    __half2 h1 = __floats2half2_rn(c, d);
    uint2 u;
    u.x = *(unsigned*)&h0;
    u.y = *(unsigned*)&h1;
    return u;
}
__device__ __forceinline__ __half2 u2h(unsigned u) { return *(__half2*)&u; }
__device__ __forceinline__ unsigned h2u(__half2 h) { return *(unsigned*)&h; }
// 2-wide fp16 tanh via MUFU.TANH.F16x2 (one MUFU op per TWO elements)
__device__ __forceinline__ float2 tanh2(float a, float b) {
    __half2 h = __floats2half2_rn(a, b);
    unsigned t;
    asm("tanh.approx.f16x2 %0, %1;" : "=r"(t) : "r"(h2u(h)));
    return __half22float2(u2h(t));
}

// ================= Launch 0: edge histograms ===============
__global__ void k_hist(const int* __restrict__ kgh, const int* __restrict__ ar) {
    int e = blockIdx.x * 256 + threadIdx.x;
    if (e < E_KG) {
        atomicAdd(&d_kg_cnt[kgh[e]], 1);
    } else {
        e -= E_KG;
        if (e < E_CF) atomicAdd(&d_ain_cnt[ar[e]], 1);
    }
}

// ================= Launch 1: init copies + PQ/cr + zero spine ===============
__global__ void k_setup2(const float* __restrict__ E0, const float* __restrict__ Wk,
                         const float* __restrict__ Wkb, const float* __restrict__ rel) {
    int b = blockIdx.x, tid = threadIdx.x;
    if (b < B_I) {
        int i = b * 256 + tid;   // exactly N_TOT*16 float4s
        float4 v = ((const float4*)E0)[i];
        ((float4*)d_sum)[i] = v;
        uint2 u = pack_h4(v.x, v.y, v.z, v.w);
        ((uint2*)d_xy16[0])[i] = u;
        if (i < N_ENT * 16) ((uint2*)d_kg16[0])[i] = u;
    } else if (b < B_I + B_P) {
        int j = (b - B_I) * 256 + tid;
        if (j < 2048) {
            int jj = j >> 4, r = j & 15;
            float s = 0.f;
            #pragma unroll
            for (int d = 0; d < 64; d++) s += Wk[jj * 64 + d] * rel[r * 64 + d];
            d_PQ[jj * 16 + r] = s;
        } else if (j < 2064) {
            int r = j - 2048;
            float s = 0.f;
            #pragma unroll
            for (int d = 0; d < 64; d++) s += Wkb[d] * rel[r * 64 + d];
            d_cr[r] = s;
        }
    } else {
        int i = (b - B_I - B_P) * 256 + tid;
        if (i < 512) d_spine[i] = 0u;
    }
}

// ================= Launch 2: At/Bt precompute + single-pass lookback scans ================
__global__ void __launch_bounds__(1024) k_atbt_scan(const float* __restrict__ E0) {
    __shared__ float sm[6144];
    int t = threadIdx.x;
    if (blockIdx.x < B_ATBT) {
        float* sPQ = sm;
        float* sE = sm + 2048;
        int nb = blockIdx.x * 64;
        for (int i = t; i < 2048; i += 1024) sPQ[i] = d_PQ[i];
        for (int i = t; i < 4096; i += 1024) {
            int rr = nb + (i >> 6);
            sE[i] = (rr < N_ENT) ? E0[(size_t)rr * 64 + (i & 63)] : 0.f;
        }
        __syncthreads();
        int ln = t >> 4, r = t & 15;
        float a = 0.f, bb = 0.f;
        #pragma unroll
        for (int j = 0; j < 64; j++) {
            float e = sE[ln * 64 + j];
            a += e * sPQ[j * 16 + r];
            bb += e * sPQ[(64 + j) * 16 + r];
        }
        int n = nb + ln;
        if (n < N_ENT) {
            d_At[(size_t)n * 16 + r] = a;
            d_Bt[(size_t)n * 16 + r] = bb;
        }
        return;
    }
    int b2 = blockIdx.x - B_ATBT;
    int which = (b2 >= NB_KG);
    int b = which ? b2 - NB_KG : b2;
    int* cnt = which ? d_ain_cnt : d_kg_cnt;
    int* rp = which ? d_ain_rp : d_kg_rp;
    int N = which ? N_TOT : N_ENT;
    int base = which ? 256 : 0;
    int* sh = (int*)sm;
    int i = b * 1024 + t;
    int v = (i < N) ? cnt[i] : 0;
    sh[t] = v;
    __syncthreads();
    for (int s = 1; s < 1024; s <<= 1) {
        int x = (t >= s) ? sh[t - s] : 0;
        __syncthreads();
        sh[t] += x;
        __syncthreads();
    }
    int agg = sh[1023];
    __shared__ int s_ex;
    if (t == 0) {
        volatile unsigned* sp = d_spine;
        if (b == 0) {
            __threadfence();
            sp[base] = (2u << 30) | (unsigned)agg;
            s_ex = 0;
        } else {
            __threadfence();
            sp[base + b] = (1u << 30) | (unsigned)agg;
            int ex = 0;
            int p = b - 1;
            while (true) {
                unsigned w;
                do { w = sp[base + p]; } while ((w >> 30) == 0u);
                ex += (int)(w & 0x3FFFFFFFu);
                if ((w >> 30) == 2u) break;
                p--;
            }
            __threadfence();
            sp[base + b] = (2u << 30) | (unsigned)(ex + agg);
            s_ex = ex;
        }
    }
    __syncthreads();
    int ex = s_ex;
    if (i < N) {
        rp[i + 1] = ex + sh[t];
        cnt[i] = ex + sh[t] - v;   // exclusive prefix -> scatter cursor
    }
    if (b == 0 && t == 0) rp[0] = 0;
}

// ========== Launch 3: merged scatter (kg: inline logit+exp; NO rowsum atomic) ==========
__global__ void k_scatter(const int* __restrict__ h, const int* __restrict__ tt_,
                          const int* __restrict__ r, const int* __restrict__ ar,
                          const int* __restrict__ ac, const float* __restrict__ av) {
    int e = blockIdx.x * blockDim.x + threadIdx.x;
    if (e < E_KG) {
        int hh = h[e], tt = tt_[e], rr = r[e];
        float l = d_At[(size_t)tt * 16 + rr] + d_Bt[(size_t)hh * 16 + rr] + d_cr[rr];
        l = (l >= 0.f) ? l : LEAKY * l;
        float ex = __expf(l);   // logits ~ N(0, 1/8): no max-subtraction needed
        int p = atomicAdd(&d_kg_cnt[hh], 1);
        d_csr_kg[p] = make_int2(tt * 128, (int)h2u(__float2half2_rn(ex)));
    } else {
        int e2 = e - E_KG;
        if (e2 >= E_CF) return;
        int p = atomicAdd(&d_ain_cnt[ar[e2]], 1);
        d_csr_ain[p] = make_int2(ac[e2] * 128, (int)h2u(__float2half2_rn(av[e2])));
    }
}

// ========== Launch 4: pre-normalize attention weights in place (warp per row) ==========
__global__ void k_norm() {
    int w = (blockIdx.x * 256 + threadIdx.x) >> 5;
    int lane = threadIdx.x & 31;
    if (w >= N_ENT) return;
    int s = d_kg_rp[w], e = d_kg_rp[w + 1];
    if (s == e) return;
    float sum = 0.f;
    for (int i = s + lane; i < e; i += 32)
        sum += __low2float(u2h((unsigned)d_csr_kg[i].y));
    #pragma unroll
    for (int o = 16; o; o >>= 1) sum += __shfl_xor_sync(~0u, sum, o);
    float inv = 1.f / sum;
    for (int i = s + lane; i < e; i += 32) {
        float a = __low2float(u2h((unsigned)d_csr_kg[i].y)) * inv;
        d_csr_kg[i].y = (int)h2u(__float2half2_rn(a));
    }
}

// ===== Launches 5,7,9: merged SpMM — 2 rows/warp, fp16 gather, HFMA2, MLP=8 =====
__global__ void __launch_bounds__(256) k_spmm(int cur) {
    int gw = (blockIdx.x * 256 + threadIdx.x) >> 5;
    int lane = threadIdx.x & 31;
    int l16 = lane & 15;
    int half = lane >> 4;
    const __half2* __restrict__ X16;
    const int2* __restrict__ csr;
    const int* __restrict__ rp;
    int row;
    bool iskg = (gw < N_ENT / 2);
    if (iskg) {
        X16 = d_kg16[cur];
        csr = d_csr_kg;
        rp = d_kg_rp;
        row = gw * 2 + half;
    } else {
        int w = gw - N_ENT / 2;
        X16 = d_xy16[cur];
        csr = d_csr_ain;
        rp = d_ain_rp;
        row = w * 2 + half;
    }
    int s = rp[row], e = rp[row + 1];
    int G = (e - s + 15) >> 4;
    int Gmax = __reduce_max_sync(0xffffffffu, G);
    float ac0 = 0.f, ac1 = 0.f, ac2 = 0.f, ac3 = 0.f;
    const char* Xb = (const char*)X16;
    int loff = l16 * 8;
    const __half2 hz = __floats2half2_rn(0.f, 0.f);
    for (int g = 0; g < Gmax; g++) {
        int idx = s + g * 16 + l16;
        int off = 0;
        unsigned ab = 0;      // half2(0,0)
        if (idx < e) {
            int2 ev = csr[idx];
            off = ev.x;
            ab = (unsigned)ev.y;
        }
        int n = e - s - g * 16;
        n = max(0, min(16, n));
        int nr = __reduce_max_sync(0xffffffffu, (n + 7) & ~7);   // pad to 8 -> MLP 8
        __half2 h0 = hz, h1 = hz, h2 = hz, h3 = hz;
        for (int j = 0; j < nr; j += 8) {
            int o0 = __shfl_sync(~0u, off, j + 0, 16), o1 = __shfl_sync(~0u, off, j + 1, 16);
            int o2 = __shfl_sync(~0u, off, j + 2, 16), o3 = __shfl_sync(~0u, off, j + 3, 16);
            int o4 = __shfl_sync(~0u, off, j + 4, 16), o5 = __shfl_sync(~0u, off, j + 5, 16);
            int o6 = __shfl_sync(~0u, off, j + 6, 16), o7 = __shfl_sync(~0u, off, j + 7, 16);
            unsigned b0 = __shfl_sync(~0u, ab, j + 0, 16), b1 = __shfl_sync(~0u, ab, j + 1, 16);
            unsigned b2 = __shfl_sync(~0u, ab, j + 2, 16), b3 = __shfl_sync(~0u, ab, j + 3, 16);
            unsigned b4 = __shfl_sync(~0u, ab, j + 4, 16), b5 = __shfl_sync(~0u, ab, j + 5, 16);
            unsigned b6 = __shfl_sync(~0u, ab, j + 6, 16), b7 = __shfl_sync(~0u, ab, j + 7, 16);
            uint2 r0 = *(const uint2*)(Xb + o0 + loff);
            uint2 r1 = *(const uint2*)(Xb + o1 + loff);
            uint2 r2 = *(const uint2*)(Xb + o2 + loff);
            uint2 r3 = *(const uint2*)(Xb + o3 + loff);
            uint2 r4 = *(const uint2*)(Xb + o4 + loff);
            uint2 r5 = *(const uint2*)(Xb + o5 + loff);
            uint2 r6 = *(const uint2*)(Xb + o6 + loff);
            uint2 r7 = *(const uint2*)(Xb + o7 + loff);
            h0 = __hfma2(u2h(b0), u2h(r0.x), h0);
            h1 = __hfma2(u2h(b0), u2h(r0.y), h1);
            h2 = __hfma2(u2h(b1), u2h(r1.x), h2);
            h3 = __hfma2(u2h(b1), u2h(r1.y), h3);
            h0 = __hfma2(u2h(b2), u2h(r2.x), h0);
            h1 = __hfma2(u2h(b2), u2h(r2.y), h1);
            h2 = __hfma2(u2h(b3), u2h(r3.x), h2);
            h3 = __hfma2(u2h(b3), u2h(r3.y), h3);
            h0 = __hfma2(u2h(b4), u2h(r4.x), h0);
            h1 = __hfma2(u2h(b4), u2h(r4.y), h1);
            h2 = __hfma2(u2h(b5), u2h(r5.x), h2);
            h3 = __hfma2(u2h(b5), u2h(r5.y), h3);
            h0 = __hfma2(u2h(b6), u2h(r6.x), h0);
            h1 = __hfma2(u2h(b6), u2h(r6.y), h1);
            h2 = __hfma2(u2h(b7), u2h(r7.x), h2);
            h3 = __hfma2(u2h(b7), u2h(r7.y), h3);
        }
        // flush half partials (<=8-term chains) into fp32 accumulators
        float2 f0 = __half22float2(h0), f1 = __half22float2(h1);
        float2 f2 = __half22float2(h2), f3 = __half22float2(h3);
        ac0 += f0.x + f2.x;
        ac1 += f0.y + f2.y;
        ac2 += f1.x + f3.x;
        ac3 += f1.y + f3.y;
    }
    if (iskg) {
        *(uint2*)((char*)d_kg16[cur ^ 1] + (size_t)row * 128 + loff) =
            pack_h4(ac0, ac1, ac2, ac3);
    } else {
        *(float4*)(d_ig + (size_t)row * 64 + l16 * 4) = make_float4(ac0, ac1, ac2, ac3);
    }
}

// ===== Launches 6,8,10: fusion gate (items, f32x2 + f16x2-tanh sigmoid) + users =====
__global__ void k_fusion_users(const float* __restrict__ Wa, const float* __restrict__ Wb,
                               int cur) {
    if (blockIdx.x >= NBF) {
        int i = (blockIdx.x - NBF) * 256 + threadIdx.x;
        if (i >= N_USR * 16) return;
        const float4* src = (const float4*)(d_ig + (size_t)N_ENT * 64);
        float4 v = src[i];
        ((uint2*)(d_xy16[cur ^ 1] + (size_t)N_ENT * 32))[i] = pack_h4(v.x, v.y, v.z, v.w);
        float4* as = (float4*)(d_sum + (size_t)N_ENT * 64);
        float4 a = as[i];
        a.x += v.x; a.y += v.y; a.z += v.z; a.w += v.w;
        as[i] = a;
        return;
    }
    __shared__ float sKG[64][68];
    __shared__ float sIG[64][68];
    const char* __restrict__ KG16 = (const char*)d_kg16[cur ^ 1];
    const float* __restrict__ IG = d_ig;
    int row0 = blockIdx.x * 64;
    int tid = threadIdx.x;  // 256
    for (int i = tid; i < 1024; i += 256) {
        int r = i >> 4, c4 = (i & 15) * 4;
        int gr = row0 + r;
        float4 kgv = make_float4(0.f, 0.f, 0.f, 0.f), igv = kgv;
        if (gr < N_ENT) {
            uint2 u = *(const uint2*)(KG16 + (size_t)gr * 128 + (i & 15) * 8);
            float2 fa = __half22float2(u2h(u.x)), fb = __half22float2(u2h(u.y));
            kgv = make_float4(fa.x, fa.y, fb.x, fb.y);
            igv = *(const float4*)(IG + (size_t)gr * 64 + c4);
        }
        *(float4*)&sKG[r][c4] = kgv;
        *(float4*)&sIG[r][c4] = igv;
    }
    __syncthreads();
    int tx = tid & 15, ty = tid >> 4;
    unsigned long long acc[4][2];
    #pragma unroll
    for (int i = 0; i < 4; i++) { acc[i][0] = 0ull; acc[i][1] = 0ull; }
    const float4* WaP = (const float4*)(Wa + tx * 4);
    const float4* WbP = (const float4*)(Wb + tx * 4);
    #pragma unroll
    for (int k4 = 0; k4 < 64; k4 += 4) {
        float4 kg[4], ig[4];
        #pragma unroll
        for (int i = 0; i < 4; i++) {
            kg[i] = *(const float4*)&sKG[ty * 4 + i][k4];
            ig[i] = *(const float4*)&sIG[ty * 4 + i][k4];
        }
        #pragma unroll
        for (int kk = 0; kk < 4; kk++) {
            float4 wav = WaP[(k4 + kk) * 16];
            float4 wbv = WbP[(k4 + kk) * 16];
            unsigned long long wa0, wa1, wb0, wb1;
            asm("mov.b64 %0, {%1, %2};" : "=l"(wa0) : "f"(wav.x), "f"(wav.y));
            asm("mov.b64 %0, {%1, %2};" : "=l"(wa1) : "f"(wav.z), "f"(wav.w));
            asm("mov.b64 %0, {%1, %2};" : "=l"(wb0) : "f"(wbv.x), "f"(wbv.y));
            asm("mov.b64 %0, {%1, %2};" : "=l"(wb1) : "f"(wbv.z), "f"(wbv.w));
            #pragma unroll
            for (int i = 0; i < 4; i++) {
                unsigned long long ks = splat2(((const float*)&kg[i])[kk]);
                unsigned long long is2 = splat2(((const float*)&ig[i])[kk]);
                fma2(acc[i][0], ks, wa0);
                fma2(acc[i][1], ks, wa1);
                fma2(acc[i][0], is2, wb0);
                fma2(acc[i][1], is2, wb1);
            }
        }
    }
    #pragma unroll
    for (int i = 0; i < 4; i++) {
        int gr = row0 + ty * 4 + i;
        if (gr >= N_ENT) break;
        float4 kgv = *(const float4*)&sKG[ty * 4 + i][tx * 4];
        float4 igv = *(const float4*)&sIG[ty * 4 + i][tx * 4];
        float s0, s1, s2, s3;
        unpack2(acc[i][0], s0, s1);
        unpack2(acc[i][1], s2, s3);
        // o = 0.5*(kg+ig) + tanh(s/2) * 0.5*(kg-ig)
        float2 t01 = tanh2(0.5f * s0, 0.5f * s1);
        float2 t23 = tanh2(0.5f * s2, 0.5f * s3);
        float4 o;
        o.x = fmaf(t01.x, 0.5f * (kgv.x - igv.x), 0.5f * (kgv.x + igv.x));
        o.y = fmaf(t01.y, 0.5f * (kgv.y - igv.y), 0.5f * (kgv.y + igv.y));
        o.z = fmaf(t23.x, 0.5f * (kgv.z - igv.z), 0.5f * (kgv.z + igv.z));
        o.w = fmaf(t23.y, 0.5f * (kgv.w - igv.w), 0.5f * (kgv.w + igv.w));
        *(uint2*)((char*)d_xy16[cur ^ 1] + (size_t)gr * 128 + tx * 8) =
            pack_h4(o.x, o.y, o.z, o.w);
        float4* as = (float4*)(d_sum + (size_t)gr * 64 + tx * 4);
        float4 a = *as;
        a.x += igv.x; a.y += igv.y; a.z += igv.z; a.w += igv.w;
        *as = a;
    }
}

// ====== Launch 11: final score GEMM + re-zero counters for the next graph replay ==========
__global__ void k_final(const int* __restrict__ uids, const int* __restrict__ iids,
                        float* __restrict__ out) {
    int bid = blockIdx.x;
    int tx = threadIdx.x, ty = threadIdx.y;
    if (bid >= 8192) {
        int t = ty * 16 + tx;
        int i = (bid - 8192) * 256 + t;
        if (i < N_ENT) d_kg_cnt[i] = 0;
        else {
            i -= N_ENT;
            if (i < N_TOT) d_ain_cnt[i] = 0;
        }
        return;
    }
    __shared__ float sU[16][68];
    __shared__ float sI[16][68];
    int ix = bid & 127, iy = bid >> 7;
    int u0 = iy * 16, i0 = ix * 16;
    {
        int ur = uids[u0 + ty];
        *(float4*)&sU[ty][tx * 4] = *(const float4*)(d_sum + (size_t)ur * 64 + tx * 4);
        int ir = iids[i0 + ty];
        *(float4*)&sI[ty][tx * 4] = *(const float4*)(d_sum + (size_t)ir * 64 + tx * 4);
    }
    __syncthreads();
    float acc = 0.f;
    #pragma unroll
    for (int k = 0; k < 64; k++) acc += sU[ty][k] * sI[tx][k];
    out[(size_t)(u0 + ty) * 2048 + i0 + tx] = acc;
}

// ---------------- launch ----------------
extern "C" void kernel_launch(void* const* d_in, const int* in_sizes, int n_in,
                              void* d_out, int out_size) {
    const float* E0   = (const float*)d_in[0];
    const float* rel  = (const float*)d_in[1];
    const float* Wk   = (const float*)d_in[2];
    const float* Wkb  = (const float*)d_in[3];
    const float* Wa   = (const float*)d_in[4];
    const float* Wb   = (const float*)d_in[5];
    const int*   kg_h = (const int*)d_in[6];
    const int*   kg_t = (const int*)d_in[7];
    const int*   kg_r = (const int*)d_in[8];
    const int*   a_r  = (const int*)d_in[9];
    const int*   a_c  = (const int*)d_in[10];
    const float* a_v  = (const float*)d_in[11];
    const int*   uids = (const int*)d_in[12];
    const int*   iids = (const int*)d_in[13];
    float* out = (float*)d_out;

    // 0: hist   1: init+PQ+spine   2: atbt+scan   3: scatter (capture slot)   4: norm
    k_hist<<<B_H, 256>>>(kg_h, a_r);
    k_setup2<<<B_I + B_P + B_S, 256>>>(E0, Wk, Wkb, rel);
    k_atbt_scan<<<B_ATBT + NB_KG + NB_AIN, 1024>>>(E0);
    k_scatter<<<B_H, 256>>>(kg_h, kg_t, kg_r, a_r, a_c, a_v);
    k_norm<<<(N_ENT * 32 + 255) / 256, 256>>>();

    int cur = 0;
    for (int l = 0; l < 3; l++) {
        // 5,7,9: spmm     6,8,10: fusion
        k_spmm<<<15625, 256>>>(cur);
        k_fusion_users<<<NBF + (N_USR * 16 + 255) / 256, 256>>>(Wa, Wb, cur);
        cur ^= 1;
    }

    dim3 fb(16, 16);
    k_final<<<8192 + 977, fb>>>(uids, iids, out);
    (void)in_sizes; (void)n_in; (void)out_size;
}

// round 15
// speedup vs baseline: 1.1184x; 1.1184x over previous
#include <cuda_runtime.h>
#include <cuda_fp16.h>
#include <math.h>

#define N_ENT 100000
#define N_USR 50000
#define N_TOT 150000
#define DIM 64
#define E_KG 1500000
#define E_CF 1500000
#define LEAKY 0.01f

#define NB_KG 98    // ceil(100000/1024)
#define NB_AIN 147  // ceil(150000/1024)
#define NBF 1563    // ceil(100000/64)

#define B_H 11719   // ceil(3,000,000/256) edge hist
#define B_I 9375    // N_TOT*16/256 init float4
#define B_P 9       // PQ + cr
#define B_Z 393     // rowsum + spine zero
#define B_ATBT 1563

// ---------------- scratch (static device globals; zero-initialized at load) ----------------
__device__ float d_PQ[128 * 16];
__device__ float d_cr[16];
__device__ float d_At[(size_t)N_ENT * 16];
__device__ float d_Bt[(size_t)N_ENT * 16];
__device__ int   d_kg_cnt[N_ENT];
__device__ int   d_kg_rp[N_ENT + 1];
__device__ int2  d_csr_kg[E_KG];            // (tail*128 byte-offset, half2(a,a) bits)
__device__ float d_rowsum[N_ENT];
__device__ int   d_ain_cnt[N_TOT];
__device__ int   d_ain_rp[N_TOT + 1];
__device__ int2  d_csr_ain[E_CF];           // (col*128 byte-offset, half2(v,v) bits)
__device__ unsigned d_spine[512];
__device__ __align__(16) __half2 d_kg16[2][(size_t)N_ENT * 32];  // fp16 gather source (kg)
__device__ __align__(16) __half2 d_xy16[2][(size_t)N_TOT * 32];  // fp16 gather source (ain)
__device__ float d_ig[(size_t)N_TOT * DIM];                      // fp32 ain-spmm out
__device__ float d_sum[(size_t)N_TOT * DIM];

// ---------------- helpers ----------------
__device__ __forceinline__ void fma2(unsigned long long& d, unsigned long long a,
                                     unsigned long long b) {
    asm("fma.rn.f32x2 %0, %1, %2, %0;" : "+l"(d) : "l"(a), "l"(b));
}
__device__ __forceinline__ unsigned long long splat2(float x) {
    unsigned long long r;
    asm("mov.b64 %0, {%1, %1};" : "=l"(r) : "r"(__float_as_uint(x)));
    return r;
}
__device__ __forceinline__ void unpack2(unsigned long long v, float& lo, float& hi) {
    unsigned a, b;
    asm("mov.b64 {%0, %1}, %2;" : "=r"(a), "=r"(b) : "l"(v));
    lo = __uint_as_float(a);
    hi = __uint_as_float(b);
}
__device__ __forceinline__ uint2 pack_h4(float a, float b, float c, float d) {
    __half2 h0 = __floats2half2_rn(a, b);
    __half2 h1 = __floats2half2_rn(c, d);
    uint2 u;
    u.x = *(unsigned*)&h0;
    u.y = *(unsigned*)&h1;
    return u;
}
__device__ __forceinline__ __half2 u2h(unsigned u) { return *(__half2*)&u; }
__device__ __forceinline__ unsigned h2u(__half2 h) { return *(unsigned*)&h; }
// 2-wide fp16 tanh via MUFU.TANH.F16x2 (one MUFU op per TWO elements)
__device__ __forceinline__ float2 tanh2(float a, float b) {
    __half2 h = __floats2half2_rn(a, b);
    unsigned t;
    asm("tanh.approx.f16x2 %0, %1;" : "=r"(t) : "r"(h2u(h)));
    return __half22float2(u2h(t));
}

// ================= Launch 0: edge histograms ===============
__global__ void k_hist(const int* __restrict__ kgh, const int* __restrict__ ar) {
    int e = blockIdx.x * 256 + threadIdx.x;
    if (e < E_KG) {
        atomicAdd(&d_kg_cnt[kgh[e]], 1);
    } else {
        e -= E_KG;
        if (e < E_CF) atomicAdd(&d_ain_cnt[ar[e]], 1);
    }
}

// ================= Launch 1: init copies + PQ/cr + zero rowsum/spine ===============
__global__ void k_setup2(const float* __restrict__ E0, const float* __restrict__ Wk,
                         const float* __restrict__ Wkb, const float* __restrict__ rel) {
    int b = blockIdx.x, tid = threadIdx.x;
    if (b < B_I) {
        int i = b * 256 + tid;   // exactly N_TOT*16 float4s
        float4 v = ((const float4*)E0)[i];
        ((float4*)d_sum)[i] = v;
        uint2 u = pack_h4(v.x, v.y, v.z, v.w);
        ((uint2*)d_xy16[0])[i] = u;
        if (i < N_ENT * 16) ((uint2*)d_kg16[0])[i] = u;
    } else if (b < B_I + B_P) {
        int j = (b - B_I) * 256 + tid;
        if (j < 2048) {
            int jj = j >> 4, r = j & 15;
            float s = 0.f;
            #pragma unroll
            for (int d = 0; d < 64; d++) s += Wk[jj * 64 + d] * rel[r * 64 + d];
            d_PQ[jj * 16 + r] = s;
        } else if (j < 2064) {
            int r = j - 2048;
            float s = 0.f;
            #pragma unroll
            for (int d = 0; d < 64; d++) s += Wkb[d] * rel[r * 64 + d];
            d_cr[r] = s;
        }
    } else {
        int i = (b - B_I - B_P) * 256 + tid;
        if (i < N_ENT) d_rowsum[i] = 0.f;
        else {
            i -= N_ENT;
            if (i < 512) d_spine[i] = 0u;
        }
    }
}

// ================= Launch 2: At/Bt precompute + single-pass lookback scans ================
__global__ void __launch_bounds__(1024) k_atbt_scan(const float* __restrict__ E0) {
    __shared__ float sm[6144];
    int t = threadIdx.x;
    if (blockIdx.x < B_ATBT) {
        float* sPQ = sm;
        float* sE = sm + 2048;
        int nb = blockIdx.x * 64;
        for (int i = t; i < 2048; i += 1024) sPQ[i] = d_PQ[i];
        for (int i = t; i < 4096; i += 1024) {
            int rr = nb + (i >> 6);
            sE[i] = (rr < N_ENT) ? E0[(size_t)rr * 64 + (i & 63)] : 0.f;
        }
        __syncthreads();
        int ln = t >> 4, r = t & 15;
        float a = 0.f, bb = 0.f;
        #pragma unroll
        for (int j = 0; j < 64; j++) {
            float e = sE[ln * 64 + j];
            a += e * sPQ[j * 16 + r];
            bb += e * sPQ[(64 + j) * 16 + r];
        }
        int n = nb + ln;
        if (n < N_ENT) {
            d_At[(size_t)n * 16 + r] = a;
            d_Bt[(size_t)n * 16 + r] = bb;
        }
        return;
    }
    int b2 = blockIdx.x - B_ATBT;
    int which = (b2 >= NB_KG);
    int b = which ? b2 - NB_KG : b2;
    int* cnt = which ? d_ain_cnt : d_kg_cnt;
    int* rp = which ? d_ain_rp : d_kg_rp;
    int N = which ? N_TOT : N_ENT;
    int base = which ? 256 : 0;
    int* sh = (int*)sm;
    int i = b * 1024 + t;
    int v = (i < N) ? cnt[i] : 0;
    sh[t] = v;
    __syncthreads();
    for (int s = 1; s < 1024; s <<= 1) {
        int x = (t >= s) ? sh[t - s] : 0;
        __syncthreads();
        sh[t] += x;
        __syncthreads();
    }
    int agg = sh[1023];
    __shared__ int s_ex;
    if (t == 0) {
        volatile unsigned* sp = d_spine;
        if (b == 0) {
            __threadfence();
            sp[base] = (2u << 30) | (unsigned)agg;
            s_ex = 0;
        } else {
            __threadfence();
            sp[base + b] = (1u << 30) | (unsigned)agg;
            int ex = 0;
            int p = b - 1;
            while (true) {
                unsigned w;
                do { w = sp[base + p]; } while ((w >> 30) == 0u);
                ex += (int)(w & 0x3FFFFFFFu);
                if ((w >> 30) == 2u) break;
                p--;
            }
            __threadfence();
            sp[base + b] = (2u << 30) | (unsigned)(ex + agg);
            s_ex = ex;
        }
    }
    __syncthreads();
    int ex = s_ex;
    if (i < N) {
        rp[i + 1] = ex + sh[t];
        cnt[i] = ex + sh[t] - v;   // exclusive prefix -> scatter cursor
    }
    if (b == 0 && t == 0) rp[0] = 0;
}

// ========== Launch 3: merged scatter (kg: inline logit+exp+rowsum; ain plain) ==========
__global__ void k_scatter(const int* __restrict__ h, const int* __restrict__ tt_,
                          const int* __restrict__ r, const int* __restrict__ ar,
                          const int* __restrict__ ac, const float* __restrict__ av) {
    int e = blockIdx.x * blockDim.x + threadIdx.x;
    if (e < E_KG) {
        int hh = h[e], tt = tt_[e], rr = r[e];
        float l = d_At[(size_t)tt * 16 + rr] + d_Bt[(size_t)hh * 16 + rr] + d_cr[rr];
        l = (l >= 0.f) ? l : LEAKY * l;
        float ex = __expf(l);   // logits ~ N(0, 1/8): no max-subtraction needed
        atomicAdd(&d_rowsum[hh], ex);
        int p = atomicAdd(&d_kg_cnt[hh], 1);
        d_csr_kg[p] = make_int2(tt * 128, (int)h2u(__float2half2_rn(ex)));
    } else {
        int e2 = e - E_KG;
        if (e2 >= E_CF) return;
        int p = atomicAdd(&d_ain_cnt[ar[e2]], 1);
        d_csr_ain[p] = make_int2(ac[e2] * 128, (int)h2u(__float2half2_rn(av[e2])));
    }
}

// ===== Launches 4,6,8: merged SpMM — 4 rows/warp (8 lanes x 16B, LDG.128), HFMA2 =====
__global__ void __launch_bounds__(256) k_spmm(int cur) {
    int gw = (blockIdx.x * 256 + threadIdx.x) >> 5;
    int lane = threadIdx.x & 31;
    int l8 = lane & 7;
    int sub = lane >> 3;          // 0..3: which of the warp's 4 rows
    const __half2* __restrict__ X16;
    const int2* __restrict__ csr;
    const int* __restrict__ rp;
    int row;
    bool iskg = (gw < N_ENT / 4);
    if (iskg) {
        X16 = d_kg16[cur];
        csr = d_csr_kg;
        rp = d_kg_rp;
        row = gw * 4 + sub;
    } else {
        int w = gw - N_ENT / 4;
        if (w >= N_TOT / 4) return;
        X16 = d_xy16[cur];
        csr = d_csr_ain;
        rp = d_ain_rp;
        row = w * 4 + sub;
    }
    int s = rp[row], e = rp[row + 1];
    int G = (e - s + 7) >> 3;
    int Gmax = __reduce_max_sync(0xffffffffu, G);
    float ac0 = 0.f, ac1 = 0.f, ac2 = 0.f, ac3 = 0.f;
    float ac4 = 0.f, ac5 = 0.f, ac6 = 0.f, ac7 = 0.f;
    const char* Xb = (const char*)X16;
    int loff = l8 * 16;           // this lane's 16B slice of the 128B row
    const __half2 hz = __floats2half2_rn(0.f, 0.f);
    for (int g = 0; g < Gmax; g++) {
        int idx = s + g * 8 + l8;
        int off = 0;
        unsigned ab = 0;          // half2(0,0)
        if (idx < e) {
            int2 ev = csr[idx];
            off = ev.x;
            ab = (unsigned)ev.y;
        }
        int n = e - s - g * 8;
        n = max(0, min(8, n));
        int nr = __reduce_max_sync(0xffffffffu, (n + 3) & ~3);   // pad to 4 (a=0 lanes noop)
        __half2 h0 = hz, h1 = hz, h2 = hz, h3 = hz;
        for (int j = 0; j < nr; j += 4) {
            int o0 = __shfl_sync(~0u, off, j + 0, 8), o1 = __shfl_sync(~0u, off, j + 1, 8);
            int o2 = __shfl_sync(~0u, off, j + 2, 8), o3 = __shfl_sync(~0u, off, j + 3, 8);
            unsigned b0 = __shfl_sync(~0u, ab, j + 0, 8), b1 = __shfl_sync(~0u, ab, j + 1, 8);
            unsigned b2 = __shfl_sync(~0u, ab, j + 2, 8), b3 = __shfl_sync(~0u, ab, j + 3, 8);
            uint4 r0 = *(const uint4*)(Xb + o0 + loff);
            uint4 r1 = *(const uint4*)(Xb + o1 + loff);
            uint4 r2 = *(const uint4*)(Xb + o2 + loff);
            uint4 r3 = *(const uint4*)(Xb + o3 + loff);
            h0 = __hfma2(u2h(b0), u2h(r0.x), h0);
            h1 = __hfma2(u2h(b0), u2h(r0.y), h1);
            h2 = __hfma2(u2h(b0), u2h(r0.z), h2);
            h3 = __hfma2(u2h(b0), u2h(r0.w), h3);
            h0 = __hfma2(u2h(b1), u2h(r1.x), h0);
            h1 = __hfma2(u2h(b1), u2h(r1.y), h1);
            h2 = __hfma2(u2h(b1), u2h(r1.z), h2);
            h3 = __hfma2(u2h(b1), u2h(r1.w), h3);
            h0 = __hfma2(u2h(b2), u2h(r2.x), h0);
            h1 = __hfma2(u2h(b2), u2h(r2.y), h1);
            h2 = __hfma2(u2h(b2), u2h(r2.z), h2);
            h3 = __hfma2(u2h(b2), u2h(r2.w), h3);
            h0 = __hfma2(u2h(b3), u2h(r3.x), h0);
            h1 = __hfma2(u2h(b3), u2h(r3.y), h1);
            h2 = __hfma2(u2h(b3), u2h(r3.z), h2);
            h3 = __hfma2(u2h(b3), u2h(r3.w), h3);
        }
        // flush half partials (<=8-term chains) into fp32 accumulators
        float2 f;
        f = __half22float2(h0); ac0 += f.x; ac1 += f.y;
        f = __half22float2(h1); ac2 += f.x; ac3 += f.y;
        f = __half22float2(h2); ac4 += f.x; ac5 += f.y;
        f = __half22float2(h3); ac6 += f.x; ac7 += f.y;
    }
    if (iskg) {
        float sc = (e > s) ? 1.f / d_rowsum[row] : 0.f;   // fold softmax normalization
        ac0 *= sc; ac1 *= sc; ac2 *= sc; ac3 *= sc;
        ac4 *= sc; ac5 *= sc; ac6 *= sc; ac7 *= sc;
        uint4 o;
        o.x = h2u(__floats2half2_rn(ac0, ac1));
        o.y = h2u(__floats2half2_rn(ac2, ac3));
        o.z = h2u(__floats2half2_rn(ac4, ac5));
        o.w = h2u(__floats2half2_rn(ac6, ac7));
        *(uint4*)((char*)d_kg16[cur ^ 1] + (size_t)row * 128 + loff) = o;
    } else {
        *(float4*)(d_ig + (size_t)row * 64 + l8 * 8) = make_float4(ac0, ac1, ac2, ac3);
        *(float4*)(d_ig + (size_t)row * 64 + l8 * 8 + 4) = make_float4(ac4, ac5, ac6, ac7);
    }
}

// ===== Launches 5,7,9: fusion gate (items, f32x2 + f16x2-tanh sigmoid) + users =====
__global__ void k_fusion_users(const float* __restrict__ Wa, const float* __restrict__ Wb,
                               int cur) {
    if (blockIdx.x >= NBF) {
        int i = (blockIdx.x - NBF) * 256 + threadIdx.x;
        if (i >= N_USR * 16) return;
        const float4* src = (const float4*)(d_ig + (size_t)N_ENT * 64);
        float4 v = src[i];
        ((uint2*)(d_xy16[cur ^ 1] + (size_t)N_ENT * 32))[i] = pack_h4(v.x, v.y, v.z, v.w);
        float4* as = (float4*)(d_sum + (size_t)N_ENT * 64);
        float4 a = as[i];
        a.x += v.x; a.y += v.y; a.z += v.z; a.w += v.w;
        as[i] = a;
        return;
    }
    __shared__ float sKG[64][68];
    __shared__ float sIG[64][68];
    const char* __restrict__ KG16 = (const char*)d_kg16[cur ^ 1];
    const float* __restrict__ IG = d_ig;
    int row0 = blockIdx.x * 64;
    int tid = threadIdx.x;  // 256
    for (int i = tid; i < 1024; i += 256) {
        int r = i >> 4, c4 = (i & 15) * 4;
        int gr = row0 + r;
        float4 kgv = make_float4(0.f, 0.f, 0.f, 0.f), igv = kgv;
        if (gr < N_ENT) {
            uint2 u = *(const uint2*)(KG16 + (size_t)gr * 128 + (i & 15) * 8);
            float2 fa = __half22float2(u2h(u.x)), fb = __half22float2(u2h(u.y));
            kgv = make_float4(fa.x, fa.y, fb.x, fb.y);
            igv = *(const float4*)(IG + (size_t)gr * 64 + c4);
        }
        *(float4*)&sKG[r][c4] = kgv;
        *(float4*)&sIG[r][c4] = igv;
    }
    __syncthreads();
    int tx = tid & 15, ty = tid >> 4;
    unsigned long long acc[4][2];
    #pragma unroll
    for (int i = 0; i < 4; i++) { acc[i][0] = 0ull; acc[i][1] = 0ull; }
    const float4* WaP = (const float4*)(Wa + tx * 4);
    const float4* WbP = (const float4*)(Wb + tx * 4);
    #pragma unroll
    for (int k4 = 0; k4 < 64; k4 += 4) {
        float4 kg[4], ig[4];
        #pragma unroll
        for (int i = 0; i < 4; i++) {
            kg[i] = *(const float4*)&sKG[ty * 4 + i][k4];
            ig[i] = *(const float4*)&sIG[ty * 4 + i][k4];
        }
        #pragma unroll
        for (int kk = 0; kk < 4; kk++) {
            float4 wav = WaP[(k4 + kk) * 16];
            float4 wbv = WbP[(k4 + kk) * 16];
            unsigned long long wa0, wa1, wb0, wb1;
            asm("mov.b64 %0, {%1, %2};" : "=l"(wa0) : "f"(wav.x), "f"(wav.y));
            asm("mov.b64 %0, {%1, %2};" : "=l"(wa1) : "f"(wav.z), "f"(wav.w));
            asm("mov.b64 %0, {%1, %2};" : "=l"(wb0) : "f"(wbv.x), "f"(wbv.y));
            asm("mov.b64 %0, {%1, %2};" : "=l"(wb1) : "f"(wbv.z), "f"(wbv.w));
            #pragma unroll
            for (int i = 0; i < 4; i++) {
                unsigned long long ks = splat2(((const float*)&kg[i])[kk]);
                unsigned long long is2 = splat2(((const float*)&ig[i])[kk]);
                fma2(acc[i][0], ks, wa0);
                fma2(acc[i][1], ks, wa1);
                fma2(acc[i][0], is2, wb0);
                fma2(acc[i][1], is2, wb1);
            }
        }
    }
    #pragma unroll
    for (int i = 0; i < 4; i++) {
        int gr = row0 + ty * 4 + i;
        if (gr >= N_ENT) break;
        float4 kgv = *(const float4*)&sKG[ty * 4 + i][tx * 4];
        float4 igv = *(const float4*)&sIG[ty * 4 + i][tx * 4];
        float s0, s1, s2, s3;
        unpack2(acc[i][0], s0, s1);
        unpack2(acc[i][1], s2, s3);
        // o = 0.5*(kg+ig) + tanh(s/2) * 0.5*(kg-ig)
        float2 t01 = tanh2(0.5f * s0, 0.5f * s1);
        float2 t23 = tanh2(0.5f * s2, 0.5f * s3);
        float4 o;
        o.x = fmaf(t01.x, 0.5f * (kgv.x - igv.x), 0.5f * (kgv.x + igv.x));
        o.y = fmaf(t01.y, 0.5f * (kgv.y - igv.y), 0.5f * (kgv.y + igv.y));
        o.z = fmaf(t23.x, 0.5f * (kgv.z - igv.z), 0.5f * (kgv.z + igv.z));
        o.w = fmaf(t23.y, 0.5f * (kgv.w - igv.w), 0.5f * (kgv.w + igv.w));
        *(uint2*)((char*)d_xy16[cur ^ 1] + (size_t)gr * 128 + tx * 8) =
            pack_h4(o.x, o.y, o.z, o.w);
        float4* as = (float4*)(d_sum + (size_t)gr * 64 + tx * 4);
        float4 a = *as;
        a.x += igv.x; a.y += igv.y; a.z += igv.z; a.w += igv.w;
        *as = a;
    }
}

// ====== Launch 10: final score GEMM + re-zero counters for the next graph replay ==========
__global__ void k_final(const int* __restrict__ uids, const int* __restrict__ iids,
                        float* __restrict__ out) {
    int bid = blockIdx.x;
    int tx = threadIdx.x, ty = threadIdx.y;
    if (bid >= 8192) {
        int t = ty * 16 + tx;
        int i = (bid - 8192) * 256 + t;
        if (i < N_ENT) d_kg_cnt[i] = 0;
        else {
            i -= N_ENT;
            if (i < N_TOT) d_ain_cnt[i] = 0;
        }
        return;
    }
    __shared__ float sU[16][68];
    __shared__ float sI[16][68];
    int ix = bid & 127, iy = bid >> 7;
    int u0 = iy * 16, i0 = ix * 16;
    {
        int ur = uids[u0 + ty];
        *(float4*)&sU[ty][tx * 4] = *(const float4*)(d_sum + (size_t)ur * 64 + tx * 4);
        int ir = iids[i0 + ty];
        *(float4*)&sI[ty][tx * 4] = *(const float4*)(d_sum + (size_t)ir * 64 + tx * 4);
    }
    __syncthreads();
    float acc = 0.f;
    #pragma unroll
    for (int k = 0; k < 64; k++) acc += sU[ty][k] * sI[tx][k];
    out[(size_t)(u0 + ty) * 2048 + i0 + tx] = acc;
}

// ---------------- launch ----------------
extern "C" void kernel_launch(void* const* d_in, const int* in_sizes, int n_in,
                              void* d_out, int out_size) {
    const float* E0   = (const float*)d_in[0];
    const float* rel  = (const float*)d_in[1];
    const float* Wk   = (const float*)d_in[2];
    const float* Wkb  = (const float*)d_in[3];
    const float* Wa   = (const float*)d_in[4];
    const float* Wb   = (const float*)d_in[5];
    const int*   kg_h = (const int*)d_in[6];
    const int*   kg_t = (const int*)d_in[7];
    const int*   kg_r = (const int*)d_in[8];
    const int*   a_r  = (const int*)d_in[9];
    const int*   a_c  = (const int*)d_in[10];
    const float* a_v  = (const float*)d_in[11];
    const int*   uids = (const int*)d_in[12];
    const int*   iids = (const int*)d_in[13];
    float* out = (float*)d_out;

    // 0: hist   1: init+PQ+zero   2: atbt+scan   3: scatter
    k_hist<<<B_H, 256>>>(kg_h, a_r);
    k_setup2<<<B_I + B_P + B_Z, 256>>>(E0, Wk, Wkb, rel);
    k_atbt_scan<<<B_ATBT + NB_KG + NB_AIN, 1024>>>(E0);
    k_scatter<<<B_H, 256>>>(kg_h, kg_t, kg_r, a_r, a_c, a_v);

    int cur = 0;
    for (int l = 0; l < 3; l++) {
        // 62,500 warps: 4 rows per warp over 250,000 total rows -> 7813 blocks
        k_spmm<<<7813, 256>>>(cur);
        k_fusion_users<<<NBF + (N_USR * 16 + 255) / 256, 256>>>(Wa, Wb, cur);
        cur ^= 1;
    }

    dim3 fb(16, 16);
    k_final<<<8192 + 977, fb>>>(uids, iids, out);
    (void)in_sizes; (void)n_in; (void)out_size;
}

// round 16
// speedup vs baseline: 1.1212x; 1.0025x over previous
#include <cuda_runtime.h>
#include <cuda_fp16.h>
#include <math.h>

#define N_ENT 100000
#define N_USR 50000
#define N_TOT 150000
#define DIM 64
#define E_KG 1500000
#define E_CF 1500000
#define LEAKY 0.01f

#define NB_KG 98    // ceil(100000/1024)
#define NB_AIN 147  // ceil(150000/1024)
#define NBF 1563    // ceil(100000/64)

#define B_H 11719   // ceil(3,000,000/256) edge hist
#define B_I 9375    // N_TOT*16/256 init float4
#define B_P 9       // PQ + cr
#define B_Z 393     // rowsum + spine zero
#define B_ATBT 1563

// ---------------- scratch (static device globals; zero-initialized at load) ----------------
__device__ float d_PQ[128 * 16];
__device__ float d_cr[16];
__device__ float d_At[(size_t)N_ENT * 16];
__device__ float d_Bt[(size_t)N_ENT * 16];
__device__ int   d_kg_cnt[N_ENT];
__device__ int   d_kg_rp[N_ENT + 1];
__device__ int2  d_csr_kg[E_KG];            // (tail*128 byte-offset, half2(a,a) bits)
__device__ float d_rowsum[N_ENT];
__device__ int   d_ain_cnt[N_TOT];
__device__ int   d_ain_rp[N_TOT + 1];
__device__ int2  d_csr_ain[E_CF];           // (col*128 byte-offset, half2(v,v) bits)
__device__ unsigned d_spine[512];
__device__ __align__(16) __half2 d_kg16[2][(size_t)N_ENT * 32];  // fp16 gather source (kg)
__device__ __align__(16) __half2 d_xy16[2][(size_t)N_TOT * 32];  // fp16 gather source (ain)
__device__ float d_ig[(size_t)N_TOT * DIM];                      // fp32 ain-spmm out
__device__ float d_sum[(size_t)N_TOT * DIM];

// ---------------- helpers ----------------
__device__ __forceinline__ void fma2(unsigned long long& d, unsigned long long a,
                                     unsigned long long b) {
    asm("fma.rn.f32x2 %0, %1, %2, %0;" : "+l"(d) : "l"(a), "l"(b));
}
__device__ __forceinline__ unsigned long long splat2(float x) {
    unsigned long long r;
    asm("mov.b64 %0, {%1, %1};" : "=l"(r) : "r"(__float_as_uint(x)));
    return r;
}
__device__ __forceinline__ void unpack2(unsigned long long v, float& lo, float& hi) {
    unsigned a, b;
    asm("mov.b64 {%0, %1}, %2;" : "=r"(a), "=r"(b) : "l"(v));
    lo = __uint_as_float(a);
    hi = __uint_as_float(b);
}
__device__ __forceinline__ uint2 pack_h4(float a, float b, float c, float d) {
    __half2 h0 = __floats2half2_rn(a, b);
    __half2 h1 = __floats2half2_rn(c, d);
    uint2 u;
    u.x = *(unsigned*)&h0;
    u.y = *(unsigned*)&h1;
    return u;
}
__device__ __forceinline__ __half2 u2h(unsigned u) { return *(__half2*)&u; }
__device__ __forceinline__ unsigned h2u(__half2 h) { return *(unsigned*)&h; }
// 2-wide fp16 tanh via MUFU.TANH.F16x2 (one MUFU op per TWO elements)
__device__ __forceinline__ float2 tanh2(float a, float b) {
    __half2 h = __floats2half2_rn(a, b);
    unsigned t;
    asm("tanh.approx.f16x2 %0, %1;" : "=r"(t) : "r"(h2u(h)));
    return __half22float2(u2h(t));
}

// ================= Launch 0: edge histograms ===============
__global__ void k_hist(const int* __restrict__ kgh, const int* __restrict__ ar) {
    int e = blockIdx.x * 256 + threadIdx.x;
    if (e < E_KG) {
        atomicAdd(&d_kg_cnt[kgh[e]], 1);
    } else {
        e -= E_KG;
        if (e < E_CF) atomicAdd(&d_ain_cnt[ar[e]], 1);
    }
}

// ================= Launch 1: init copies + PQ/cr + zero rowsum/spine ===============
__global__ void k_setup2(const float* __restrict__ E0, const float* __restrict__ Wk,
                         const float* __restrict__ Wkb, const float* __restrict__ rel) {
    int b = blockIdx.x, tid = threadIdx.x;
    if (b < B_I) {
        int i = b * 256 + tid;   // exactly N_TOT*16 float4s
        float4 v = ((const float4*)E0)[i];
        ((float4*)d_sum)[i] = v;
        uint2 u = pack_h4(v.x, v.y, v.z, v.w);
        ((uint2*)d_xy16[0])[i] = u;
        if (i < N_ENT * 16) ((uint2*)d_kg16[0])[i] = u;
    } else if (b < B_I + B_P) {
        int j = (b - B_I) * 256 + tid;
        if (j < 2048) {
            int jj = j >> 4, r = j & 15;
            float s = 0.f;
            #pragma unroll
            for (int d = 0; d < 64; d++) s += Wk[jj * 64 + d] * rel[r * 64 + d];
            d_PQ[jj * 16 + r] = s;
        } else if (j < 2064) {
            int r = j - 2048;
            float s = 0.f;
            #pragma unroll
            for (int d = 0; d < 64; d++) s += Wkb[d] * rel[r * 64 + d];
            d_cr[r] = s;
        }
    } else {
        int i = (b - B_I - B_P) * 256 + tid;
        if (i < N_ENT) d_rowsum[i] = 0.f;
        else {
            i -= N_ENT;
            if (i < 512) d_spine[i] = 0u;
        }
    }
}

// ================= Launch 2: At/Bt precompute + single-pass lookback scans ================
__global__ void __launch_bounds__(1024) k_atbt_scan(const float* __restrict__ E0) {
    __shared__ float sm[6144];
    int t = threadIdx.x;
    if (blockIdx.x < B_ATBT) {
        float* sPQ = sm;
        float* sE = sm + 2048;
        int nb = blockIdx.x * 64;
        for (int i = t; i < 2048; i += 1024) sPQ[i] = d_PQ[i];
        for (int i = t; i < 4096; i += 1024) {
            int rr = nb + (i >> 6);
            sE[i] = (rr < N_ENT) ? E0[(size_t)rr * 64 + (i & 63)] : 0.f;
        }
        __syncthreads();
        int ln = t >> 4, r = t & 15;
        float a = 0.f, bb = 0.f;
        #pragma unroll
        for (int j = 0; j < 64; j++) {
            float e = sE[ln * 64 + j];
            a += e * sPQ[j * 16 + r];
            bb += e * sPQ[(64 + j) * 16 + r];
        }
        int n = nb + ln;
        if (n < N_ENT) {
            d_At[(size_t)n * 16 + r] = a;
            d_Bt[(size_t)n * 16 + r] = bb;
        }
        return;
    }
    int b2 = blockIdx.x - B_ATBT;
    int which = (b2 >= NB_KG);
    int b = which ? b2 - NB_KG : b2;
    int* cnt = which ? d_ain_cnt : d_kg_cnt;
    int* rp = which ? d_ain_rp : d_kg_rp;
    int N = which ? N_TOT : N_ENT;
    int base = which ? 256 : 0;
    int* sh = (int*)sm;
    int i = b * 1024 + t;
    int v = (i < N) ? cnt[i] : 0;
    sh[t] = v;
    __syncthreads();
    for (int s = 1; s < 1024; s <<= 1) {
        int x = (t >= s) ? sh[t - s] : 0;
        __syncthreads();
        sh[t] += x;
        __syncthreads();
    }
    int agg = sh[1023];
    __shared__ int s_ex;
    if (t == 0) {
        volatile unsigned* sp = d_spine;
        if (b == 0) {
            __threadfence();
            sp[base] = (2u << 30) | (unsigned)agg;
            s_ex = 0;
        } else {
            __threadfence();
            sp[base + b] = (1u << 30) | (unsigned)agg;
            int ex = 0;
            int p = b - 1;
            while (true) {
                unsigned w;
                do { w = sp[base + p]; } while ((w >> 30) == 0u);
                ex += (int)(w & 0x3FFFFFFFu);
                if ((w >> 30) == 2u) break;
                p--;
            }
            __threadfence();
            sp[base + b] = (2u << 30) | (unsigned)(ex + agg);
            s_ex = ex;
        }
    }
    __syncthreads();
    int ex = s_ex;
    if (i < N) {
        rp[i + 1] = ex + sh[t];
        cnt[i] = ex + sh[t] - v;   // exclusive prefix -> scatter cursor
    }
    if (b == 0 && t == 0) rp[0] = 0;
}

// ========== Launch 3: merged scatter (kg: inline logit+exp+rowsum; ain plain) ==========
__global__ void k_scatter(const int* __restrict__ h, const int* __restrict__ tt_,
                          const int* __restrict__ r, const int* __restrict__ ar,
                          const int* __restrict__ ac, const float* __restrict__ av) {
    int e = blockIdx.x * blockDim.x + threadIdx.x;
    if (e < E_KG) {
        int hh = h[e], tt = tt_[e], rr = r[e];
        float l = d_At[(size_t)tt * 16 + rr] + d_Bt[(size_t)hh * 16 + rr] + d_cr[rr];
        l = (l >= 0.f) ? l : LEAKY * l;
        float ex = __expf(l);   // logits ~ N(0, 1/8): no max-subtraction needed
        atomicAdd(&d_rowsum[hh], ex);
        int p = atomicAdd(&d_kg_cnt[hh], 1);
        d_csr_kg[p] = make_int2(tt * 128, (int)h2u(__float2half2_rn(ex)));
    } else {
        int e2 = e - E_KG;
        if (e2 >= E_CF) return;
        int p = atomicAdd(&d_ain_cnt[ar[e2]], 1);
        d_csr_ain[p] = make_int2(ac[e2] * 128, (int)h2u(__float2half2_rn(av[e2])));
    }
}

// ===== Launches 4,6,8: merged SpMM — 4 rows/warp, LDG.128 gathers, pipelined staging =====
__global__ void __launch_bounds__(256) k_spmm(int cur) {
    int gw = (blockIdx.x * 256 + threadIdx.x) >> 5;
    int lane = threadIdx.x & 31;
    int l8 = lane & 7;
    int sub = lane >> 3;          // 0..3: which of the warp's 4 rows
    const __half2* __restrict__ X16;
    const int2* __restrict__ csr;
    const int* __restrict__ rp;
    int row;
    bool iskg = (gw < N_ENT / 4);
    if (iskg) {
        X16 = d_kg16[cur];
        csr = d_csr_kg;
        rp = d_kg_rp;
        row = gw * 4 + sub;
    } else {
        int w = gw - N_ENT / 4;
        if (w >= N_TOT / 4) return;
        X16 = d_xy16[cur];
        csr = d_csr_ain;
        rp = d_ain_rp;
        row = w * 4 + sub;
    }
    int s = rp[row], e = rp[row + 1];
    int G = (e - s + 7) >> 3;
    int Gmax = __reduce_max_sync(0xffffffffu, G);
    float ac0 = 0.f, ac1 = 0.f, ac2 = 0.f, ac3 = 0.f;
    float ac4 = 0.f, ac5 = 0.f, ac6 = 0.f, ac7 = 0.f;
    const char* Xb = (const char*)X16;
    int loff = l8 * 16;           // this lane's 16B slice of the 128B row
    const __half2 hz = __floats2half2_rn(0.f, 0.f);
    // -------- software pipeline: prefetch group 0's edge entries --------
    int off_n = 0;
    unsigned ab_n = 0;
    {
        int idx = s + l8;
        if (idx < e) {
            int2 ev = csr[idx];
            off_n = ev.x;
            ab_n = (unsigned)ev.y;
        }
    }
    for (int g = 0; g < Gmax; g++) {
        int off = off_n;
        unsigned ab = ab_n;
        // prefetch group g+1 BEFORE the gather chain: its ~L2 latency overlaps
        // this group's shfl+gather+hfma work (removes one L2 hop from critical path)
        off_n = 0;
        ab_n = 0;
        int idx2 = s + (g + 1) * 8 + l8;
        if (idx2 < e) {
            int2 ev = csr[idx2];
            off_n = ev.x;
            ab_n = (unsigned)ev.y;
        }
        int n = e - s - g * 8;
        n = max(0, min(8, n));
        int nr = __reduce_max_sync(0xffffffffu, (n + 3) & ~3);   // pad to 4 (a=0 lanes noop)
        __half2 h0 = hz, h1 = hz, h2 = hz, h3 = hz;
        for (int j = 0; j < nr; j += 4) {
            int o0 = __shfl_sync(~0u, off, j + 0, 8), o1 = __shfl_sync(~0u, off, j + 1, 8);
            int o2 = __shfl_sync(~0u, off, j + 2, 8), o3 = __shfl_sync(~0u, off, j + 3, 8);
            unsigned b0 = __shfl_sync(~0u, ab, j + 0, 8), b1 = __shfl_sync(~0u, ab, j + 1, 8);
            unsigned b2 = __shfl_sync(~0u, ab, j + 2, 8), b3 = __shfl_sync(~0u, ab, j + 3, 8);
            uint4 r0 = *(const uint4*)(Xb + o0 + loff);
            uint4 r1 = *(const uint4*)(Xb + o1 + loff);
            uint4 r2 = *(const uint4*)(Xb + o2 + loff);
            uint4 r3 = *(const uint4*)(Xb + o3 + loff);
            h0 = __hfma2(u2h(b0), u2h(r0.x), h0);
            h1 = __hfma2(u2h(b0), u2h(r0.y), h1);
            h2 = __hfma2(u2h(b0), u2h(r0.z), h2);
            h3 = __hfma2(u2h(b0), u2h(r0.w), h3);
            h0 = __hfma2(u2h(b1), u2h(r1.x), h0);
            h1 = __hfma2(u2h(b1), u2h(r1.y), h1);
            h2 = __hfma2(u2h(b1), u2h(r1.z), h2);
            h3 = __hfma2(u2h(b1), u2h(r1.w), h3);
            h0 = __hfma2(u2h(b2), u2h(r2.x), h0);
            h1 = __hfma2(u2h(b2), u2h(r2.y), h1);
            h2 = __hfma2(u2h(b2), u2h(r2.z), h2);
            h3 = __hfma2(u2h(b2), u2h(r2.w), h3);
            h0 = __hfma2(u2h(b3), u2h(r3.x), h0);
            h1 = __hfma2(u2h(b3), u2h(r3.y), h1);
            h2 = __hfma2(u2h(b3), u2h(r3.z), h2);
            h3 = __hfma2(u2h(b3), u2h(r3.w), h3);
        }
        // flush half partials (<=8-term chains) into fp32 accumulators
        float2 f;
        f = __half22float2(h0); ac0 += f.x; ac1 += f.y;
        f = __half22float2(h1); ac2 += f.x; ac3 += f.y;
        f = __half22float2(h2); ac4 += f.x; ac5 += f.y;
        f = __half22float2(h3); ac6 += f.x; ac7 += f.y;
    }
    if (iskg) {
        float sc = (e > s) ? 1.f / d_rowsum[row] : 0.f;   // fold softmax normalization
        ac0 *= sc; ac1 *= sc; ac2 *= sc; ac3 *= sc;
        ac4 *= sc; ac5 *= sc; ac6 *= sc; ac7 *= sc;
        uint4 o;
        o.x = h2u(__floats2half2_rn(ac0, ac1));
        o.y = h2u(__floats2half2_rn(ac2, ac3));
        o.z = h2u(__floats2half2_rn(ac4, ac5));
        o.w = h2u(__floats2half2_rn(ac6, ac7));
        *(uint4*)((char*)d_kg16[cur ^ 1] + (size_t)row * 128 + loff) = o;
    } else {
        *(float4*)(d_ig + (size_t)row * 64 + l8 * 8) = make_float4(ac0, ac1, ac2, ac3);
        *(float4*)(d_ig + (size_t)row * 64 + l8 * 8 + 4) = make_float4(ac4, ac5, ac6, ac7);
    }
}

// ===== Launches 5,7,9: fusion gate (items, f32x2 + f16x2-tanh sigmoid) + users =====
__global__ void k_fusion_users(const float* __restrict__ Wa, const float* __restrict__ Wb,
                               int cur) {
    if (blockIdx.x >= NBF) {
        int i = (blockIdx.x - NBF) * 256 + threadIdx.x;
        if (i >= N_USR * 16) return;
        const float4* src = (const float4*)(d_ig + (size_t)N_ENT * 64);
        float4 v = src[i];
        ((uint2*)(d_xy16[cur ^ 1] + (size_t)N_ENT * 32))[i] = pack_h4(v.x, v.y, v.z, v.w);
        float4* as = (float4*)(d_sum + (size_t)N_ENT * 64);
        float4 a = as[i];
        a.x += v.x; a.y += v.y; a.z += v.z; a.w += v.w;
        as[i] = a;
        return;
    }
    __shared__ float sKG[64][68];
    __shared__ float sIG[64][68];
    const char* __restrict__ KG16 = (const char*)d_kg16[cur ^ 1];
    const float* __restrict__ IG = d_ig;
    int row0 = blockIdx.x * 64;
    int tid = threadIdx.x;  // 256
    for (int i = tid; i < 1024; i += 256) {
        int r = i >> 4, c4 = (i & 15) * 4;
        int gr = row0 + r;
        float4 kgv = make_float4(0.f, 0.f, 0.f, 0.f), igv = kgv;
        if (gr < N_ENT) {
            uint2 u = *(const uint2*)(KG16 + (size_t)gr * 128 + (i & 15) * 8);
            float2 fa = __half22float2(u2h(u.x)), fb = __half22float2(u2h(u.y));
            kgv = make_float4(fa.x, fa.y, fb.x, fb.y);
            igv = *(const float4*)(IG + (size_t)gr * 64 + c4);
        }
        *(float4*)&sKG[r][c4] = kgv;
        *(float4*)&sIG[r][c4] = igv;
    }
    __syncthreads();
    int tx = tid & 15, ty = tid >> 4;
    unsigned long long acc[4][2];
    #pragma unroll
    for (int i = 0; i < 4; i++) { acc[i][0] = 0ull; acc[i][1] = 0ull; }
    const float4* WaP = (const float4*)(Wa + tx * 4);
    const float4* WbP = (const float4*)(Wb + tx * 4);
    #pragma unroll
    for (int k4 = 0; k4 < 64; k4 += 4) {
        float4 kg[4], ig[4];
        #pragma unroll
        for (int i = 0; i < 4; i++) {
            kg[i] = *(const float4*)&sKG[ty * 4 + i][k4];
            ig[i] = *(const float4*)&sIG[ty * 4 + i][k4];
        }
        #pragma unroll
        for (int kk = 0; kk < 4; kk++) {
            float4 wav = WaP[(k4 + kk) * 16];
            float4 wbv = WbP[(k4 + kk) * 16];
            unsigned long long wa0, wa1, wb0, wb1;
            asm("mov.b64 %0, {%1, %2};" : "=l"(wa0) : "f"(wav.x), "f"(wav.y));
            asm("mov.b64 %0, {%1, %2};" : "=l"(wa1) : "f"(wav.z), "f"(wav.w));
            asm("mov.b64 %0, {%1, %2};" : "=l"(wb0) : "f"(wbv.x), "f"(wbv.y));
            asm("mov.b64 %0, {%1, %2};" : "=l"(wb1) : "f"(wbv.z), "f"(wbv.w));
            #pragma unroll
            for (int i = 0; i < 4; i++) {
                unsigned long long ks = splat2(((const float*)&kg[i])[kk]);
                unsigned long long is2 = splat2(((const float*)&ig[i])[kk]);
                fma2(acc[i][0], ks, wa0);
                fma2(acc[i][1], ks, wa1);
                fma2(acc[i][0], is2, wb0);
                fma2(acc[i][1], is2, wb1);
            }
        }
    }
    #pragma unroll
    for (int i = 0; i < 4; i++) {
        int gr = row0 + ty * 4 + i;
        if (gr >= N_ENT) break;
        float4 kgv = *(const float4*)&sKG[ty * 4 + i][tx * 4];
        float4 igv = *(const float4*)&sIG[ty * 4 + i][tx * 4];
        float s0, s1, s2, s3;
        unpack2(acc[i][0], s0, s1);
        unpack2(acc[i][1], s2, s3);
        // o = 0.5*(kg+ig) + tanh(s/2) * 0.5*(kg-ig)
        float2 t01 = tanh2(0.5f * s0, 0.5f * s1);
        float2 t23 = tanh2(0.5f * s2, 0.5f * s3);
        float4 o;
        o.x = fmaf(t01.x, 0.5f * (kgv.x - igv.x), 0.5f * (kgv.x + igv.x));
        o.y = fmaf(t01.y, 0.5f * (kgv.y - igv.y), 0.5f * (kgv.y + igv.y));
        o.z = fmaf(t23.x, 0.5f * (kgv.z - igv.z), 0.5f * (kgv.z + igv.z));
        o.w = fmaf(t23.y, 0.5f * (kgv.w - igv.w), 0.5f * (kgv.w + igv.w));
        *(uint2*)((char*)d_xy16[cur ^ 1] + (size_t)gr * 128 + tx * 8) =
            pack_h4(o.x, o.y, o.z, o.w);
        float4* as = (float4*)(d_sum + (size_t)gr * 64 + tx * 4);
        float4 a = *as;
        a.x += igv.x; a.y += igv.y; a.z += igv.z; a.w += igv.w;
        *as = a;
    }
}

// ====== Launch 10: final score GEMM + re-zero counters for the next graph replay ==========
__global__ void k_final(const int* __restrict__ uids, const int* __restrict__ iids,
                        float* __restrict__ out) {
    int bid = blockIdx.x;
    int tx = threadIdx.x, ty = threadIdx.y;
    if (bid >= 8192) {
        int t = ty * 16 + tx;
        int i = (bid - 8192) * 256 + t;
        if (i < N_ENT) d_kg_cnt[i] = 0;
        else {
            i -= N_ENT;
            if (i < N_TOT) d_ain_cnt[i] = 0;
        }
        return;
    }
    __shared__ float sU[16][68];
    __shared__ float sI[16][68];
    int ix = bid & 127, iy = bid >> 7;
    int u0 = iy * 16, i0 = ix * 16;
    {
        int ur = uids[u0 + ty];
        *(float4*)&sU[ty][tx * 4] = *(const float4*)(d_sum + (size_t)ur * 64 + tx * 4);
        int ir = iids[i0 + ty];
        *(float4*)&sI[ty][tx * 4] = *(const float4*)(d_sum + (size_t)ir * 64 + tx * 4);
    }
    __syncthreads();
    float acc = 0.f;
    #pragma unroll
    for (int k = 0; k < 64; k++) acc += sU[ty][k] * sI[tx][k];
    out[(size_t)(u0 + ty) * 2048 + i0 + tx] = acc;
}

// ---------------- launch ----------------
extern "C" void kernel_launch(void* const* d_in, const int* in_sizes, int n_in,
                              void* d_out, int out_size) {
    const float* E0   = (const float*)d_in[0];
    const float* rel  = (const float*)d_in[1];
    const float* Wk   = (const float*)d_in[2];
    const float* Wkb  = (const float*)d_in[3];
    const float* Wa   = (const float*)d_in[4];
    const float* Wb   = (const float*)d_in[5];
    const int*   kg_h = (const int*)d_in[6];
    const int*   kg_t = (const int*)d_in[7];
    const int*   kg_r = (const int*)d_in[8];
    const int*   a_r  = (const int*)d_in[9];
    const int*   a_c  = (const int*)d_in[10];
    const float* a_v  = (const float*)d_in[11];
    const int*   uids = (const int*)d_in[12];
    const int*   iids = (const int*)d_in[13];
    float* out = (float*)d_out;

    // 0: hist   1: init+PQ+zero   2: atbt+scan   3: scatter (capture slot)
    k_hist<<<B_H, 256>>>(kg_h, a_r);
    k_setup2<<<B_I + B_P + B_Z, 256>>>(E0, Wk, Wkb, rel);
    k_atbt_scan<<<B_ATBT + NB_KG + NB_AIN, 1024>>>(E0);
    k_scatter<<<B_H, 256>>>(kg_h, kg_t, kg_r, a_r, a_c, a_v);

    int cur = 0;
    for (int l = 0; l < 3; l++) {
        // 62,500 warps: 4 rows per warp over 250,000 total rows -> 7813 blocks
        k_spmm<<<7813, 256>>>(cur);
        k_fusion_users<<<NBF + (N_USR * 16 + 255) / 256, 256>>>(Wa, Wb, cur);
        cur ^= 1;
    }

    dim3 fb(16, 16);
    k_final<<<8192 + 977, fb>>>(uids, iids, out);
    (void)in_sizes; (void)n_in; (void)out_size;
}

// round 17
// speedup vs baseline: 1.3731x; 1.2247x over previous
#include <cuda_runtime.h>
#include <cuda_fp16.h>
#include <math.h>

#define N_ENT 100000
#define N_USR 50000
#define N_TOT 150000
#define DIM 64
#define E_KG 1500000
#define E_CF 1500000
#define LEAKY 0.01f

#define NB_KG 98    // ceil(100000/1024)
#define NB_AIN 147  // ceil(150000/1024)
#define NBF 1563    // ceil(100000/64)

#define B_H 11719   // ceil(3,000,000/256) edge hist
#define B_I 9375    // N_TOT*16/256 init float4
#define B_P 9       // PQ + cr
#define B_W 32      // Wa/Wb -> fp16 combined weight (8192 elems)
#define B_Z 393     // rowsum + spine zero
#define B_ATBT 1563

// ---------------- scratch (static device globals; zero-initialized at load) ----------------
__device__ float d_PQ[128 * 16];
__device__ float d_cr[16];
__device__ float d_At[(size_t)N_ENT * 16];
__device__ float d_Bt[(size_t)N_ENT * 16];
__device__ int   d_kg_cnt[N_ENT];
__device__ int   d_kg_rp[N_ENT + 1];
__device__ int2  d_csr_kg[E_KG];            // (tail*128 byte-offset, half2(a,a) bits)
__device__ float d_rowsum[N_ENT];
__device__ int   d_ain_cnt[N_TOT];
__device__ int   d_ain_rp[N_TOT + 1];
__device__ int2  d_csr_ain[E_CF];           // (col*128 byte-offset, half2(v,v) bits)
__device__ unsigned d_spine[512];
__device__ __align__(16) __half d_w16[128 * 64];   // [Wa; Wb] fp16, row k, col j
__device__ __align__(16) __half2 d_kg16[2][(size_t)N_ENT * 32];  // fp16 gather source (kg)
__device__ __align__(16) __half2 d_xy16[2][(size_t)N_TOT * 32];  // fp16 gather source (ain)
__device__ float d_ig[(size_t)N_TOT * DIM];                      // fp32 ain-spmm out
__device__ float d_sum[(size_t)N_TOT * DIM];

// ---------------- helpers ----------------
__device__ __forceinline__ uint2 pack_h4(float a, float b, float c, float d) {
    __half2 h0 = __floats2half2_rn(a, b);
    __half2 h1 = __floats2half2_rn(c, d);
    uint2 u;
    u.x = *(unsigned*)&h0;
    u.y = *(unsigned*)&h1;
    return u;
}
__device__ __forceinline__ __half2 u2h(unsigned u) { return *(__half2*)&u; }
__device__ __forceinline__ unsigned h2u(__half2 h) { return *(unsigned*)&h; }
// 2-wide fp16 tanh via MUFU.TANH.F16x2
__device__ __forceinline__ float2 tanh2(float a, float b) {
    __half2 h = __floats2half2_rn(a, b);
    unsigned t;
    asm("tanh.approx.f16x2 %0, %1;" : "=r"(t) : "r"(h2u(h)));
    return __half22float2(u2h(t));
}
__device__ __forceinline__ void ldsm_x4(unsigned& r0, unsigned& r1, unsigned& r2, unsigned& r3,
                                        unsigned addr) {
    asm volatile("ldmatrix.sync.aligned.m8n8.x4.shared.b16 {%0,%1,%2,%3}, [%4];"
                 : "=r"(r0), "=r"(r1), "=r"(r2), "=r"(r3) : "r"(addr));
}
__device__ __forceinline__ void ldsm_x2t(unsigned& r0, unsigned& r1, unsigned addr) {
    asm volatile("ldmatrix.sync.aligned.m8n8.x2.trans.shared.b16 {%0,%1}, [%2];"
                 : "=r"(r0), "=r"(r1) : "r"(addr));
}
__device__ __forceinline__ void mma16816(float* d, unsigned a0, unsigned a1, unsigned a2,
                                         unsigned a3, unsigned b0, unsigned b1) {
    asm volatile("mma.sync.aligned.m16n8k16.row.col.f32.f16.f16.f32 "
                 "{%0,%1,%2,%3}, {%4,%5,%6,%7}, {%8,%9}, {%0,%1,%2,%3};"
                 : "+f"(d[0]), "+f"(d[1]), "+f"(d[2]), "+f"(d[3])
                 : "r"(a0), "r"(a1), "r"(a2), "r"(a3), "r"(b0), "r"(b1));
}

// ================= Launch 0: edge histograms ===============
__global__ void k_hist(const int* __restrict__ kgh, const int* __restrict__ ar) {
    int e = blockIdx.x * 256 + threadIdx.x;
    if (e < E_KG) {
        atomicAdd(&d_kg_cnt[kgh[e]], 1);
    } else {
        e -= E_KG;
        if (e < E_CF) atomicAdd(&d_ain_cnt[ar[e]], 1);
    }
}

// ========= Launch 1: init copies + PQ/cr + weight fp16 conversion + zero rowsum/spine =====
__global__ void k_setup2(const float* __restrict__ E0, const float* __restrict__ Wk,
                         const float* __restrict__ Wkb, const float* __restrict__ rel,
                         const float* __restrict__ Wa, const float* __restrict__ Wb) {
    int b = blockIdx.x, tid = threadIdx.x;
    if (b < B_I) {
        int i = b * 256 + tid;   // exactly N_TOT*16 float4s
        float4 v = ((const float4*)E0)[i];
        ((float4*)d_sum)[i] = v;
        uint2 u = pack_h4(v.x, v.y, v.z, v.w);
        ((uint2*)d_xy16[0])[i] = u;
        if (i < N_ENT * 16) ((uint2*)d_kg16[0])[i] = u;
    } else if (b < B_I + B_P) {
        int j = (b - B_I) * 256 + tid;
        if (j < 2048) {
            int jj = j >> 4, r = j & 15;
            float s = 0.f;
            #pragma unroll
            for (int d = 0; d < 64; d++) s += Wk[jj * 64 + d] * rel[r * 64 + d];
            d_PQ[jj * 16 + r] = s;
        } else if (j < 2064) {
            int r = j - 2048;
            float s = 0.f;
            #pragma unroll
            for (int d = 0; d < 64; d++) s += Wkb[d] * rel[r * 64 + d];
            d_cr[r] = s;
        }
    } else if (b < B_I + B_P + B_W) {
        int j = (b - B_I - B_P) * 256 + tid;   // 0..8191
        int k = j >> 6, c = j & 63;
        float v = (k < 64) ? Wa[k * 64 + c] : Wb[(k - 64) * 64 + c];
        d_w16[j] = __float2half(v);
    } else {
        int i = (b - B_I - B_P - B_W) * 256 + tid;
        if (i < N_ENT) d_rowsum[i] = 0.f;
        else {
            i -= N_ENT;
            if (i < 512) d_spine[i] = 0u;
        }
    }
}

// ================= Launch 2: At/Bt precompute + single-pass lookback scans ================
__global__ void __launch_bounds__(1024) k_atbt_scan(const float* __restrict__ E0) {
    __shared__ float sm[6144];
    int t = threadIdx.x;
    if (blockIdx.x < B_ATBT) {
        float* sPQ = sm;
        float* sE = sm + 2048;
        int nb = blockIdx.x * 64;
        for (int i = t; i < 2048; i += 1024) sPQ[i] = d_PQ[i];
        for (int i = t; i < 4096; i += 1024) {
            int rr = nb + (i >> 6);
            sE[i] = (rr < N_ENT) ? E0[(size_t)rr * 64 + (i & 63)] : 0.f;
        }
        __syncthreads();
        int ln = t >> 4, r = t & 15;
        float a = 0.f, bb = 0.f;
        #pragma unroll
        for (int j = 0; j < 64; j++) {
            float e = sE[ln * 64 + j];
            a += e * sPQ[j * 16 + r];
            bb += e * sPQ[(64 + j) * 16 + r];
        }
        int n = nb + ln;
        if (n < N_ENT) {
            d_At[(size_t)n * 16 + r] = a;
            d_Bt[(size_t)n * 16 + r] = bb;
        }
        return;
    }
    int b2 = blockIdx.x - B_ATBT;
    int which = (b2 >= NB_KG);
    int b = which ? b2 - NB_KG : b2;
    int* cnt = which ? d_ain_cnt : d_kg_cnt;
    int* rp = which ? d_ain_rp : d_kg_rp;
    int N = which ? N_TOT : N_ENT;
    int base = which ? 256 : 0;
    int* sh = (int*)sm;
    int i = b * 1024 + t;
    int v = (i < N) ? cnt[i] : 0;
    sh[t] = v;
    __syncthreads();
    for (int s = 1; s < 1024; s <<= 1) {
        int x = (t >= s) ? sh[t - s] : 0;
        __syncthreads();
        sh[t] += x;
        __syncthreads();
    }
    int agg = sh[1023];
    __shared__ int s_ex;
    if (t == 0) {
        volatile unsigned* sp = d_spine;
        if (b == 0) {
            __threadfence();
            sp[base] = (2u << 30) | (unsigned)agg;
            s_ex = 0;
        } else {
            __threadfence();
            sp[base + b] = (1u << 30) | (unsigned)agg;
            int ex = 0;
            int p = b - 1;
            while (true) {
                unsigned w;
                do { w = sp[base + p]; } while ((w >> 30) == 0u);
                ex += (int)(w & 0x3FFFFFFFu);
                if ((w >> 30) == 2u) break;
                p--;
            }
            __threadfence();
            sp[base + b] = (2u << 30) | (unsigned)(ex + agg);
            s_ex = ex;
        }
    }
    __syncthreads();
    int ex = s_ex;
    if (i < N) {
        rp[i + 1] = ex + sh[t];
        cnt[i] = ex + sh[t] - v;   // exclusive prefix -> scatter cursor
    }
    if (b == 0 && t == 0) rp[0] = 0;
}

// ========== Launch 3: merged scatter (kg: inline logit+exp+rowsum; ain plain) ==========
__global__ void k_scatter(const int* __restrict__ h, const int* __restrict__ tt_,
                          const int* __restrict__ r, const int* __restrict__ ar,
                          const int* __restrict__ ac, const float* __restrict__ av) {
    int e = blockIdx.x * blockDim.x + threadIdx.x;
    if (e < E_KG) {
        int hh = h[e], tt = tt_[e], rr = r[e];
        float l = d_At[(size_t)tt * 16 + rr] + d_Bt[(size_t)hh * 16 + rr] + d_cr[rr];
        l = (l >= 0.f) ? l : LEAKY * l;
        float ex = __expf(l);   // logits ~ N(0, 1/8): no max-subtraction needed
        atomicAdd(&d_rowsum[hh], ex);
        int p = atomicAdd(&d_kg_cnt[hh], 1);
        d_csr_kg[p] = make_int2(tt * 128, (int)h2u(__float2half2_rn(ex)));
    } else {
        int e2 = e - E_KG;
        if (e2 >= E_CF) return;
        int p = atomicAdd(&d_ain_cnt[ar[e2]], 1);
        d_csr_ain[p] = make_int2(ac[e2] * 128, (int)h2u(__float2half2_rn(av[e2])));
    }
}

// ===== Launches 4,6,8: merged SpMM — 4 rows/warp, LDG.128 gathers, pipelined staging =====
__global__ void __launch_bounds__(256) k_spmm(int cur) {
    int gw = (blockIdx.x * 256 + threadIdx.x) >> 5;
    int lane = threadIdx.x & 31;
    int l8 = lane & 7;
    int sub = lane >> 3;          // 0..3: which of the warp's 4 rows
    const __half2* __restrict__ X16;
    const int2* __restrict__ csr;
    const int* __restrict__ rp;
    int row;
    bool iskg = (gw < N_ENT / 4);
    if (iskg) {
        X16 = d_kg16[cur];
        csr = d_csr_kg;
        rp = d_kg_rp;
        row = gw * 4 + sub;
    } else {
        int w = gw - N_ENT / 4;
        if (w >= N_TOT / 4) return;
        X16 = d_xy16[cur];
        csr = d_csr_ain;
        rp = d_ain_rp;
        row = w * 4 + sub;
    }
    int s = rp[row], e = rp[row + 1];
    int G = (e - s + 7) >> 3;
    int Gmax = __reduce_max_sync(0xffffffffu, G);
    float ac0 = 0.f, ac1 = 0.f, ac2 = 0.f, ac3 = 0.f;
    float ac4 = 0.f, ac5 = 0.f, ac6 = 0.f, ac7 = 0.f;
    const char* Xb = (const char*)X16;
    int loff = l8 * 16;           // this lane's 16B slice of the 128B row
    const __half2 hz = __floats2half2_rn(0.f, 0.f);
    int off_n = 0;
    unsigned ab_n = 0;
    {
        int idx = s + l8;
        if (idx < e) {
            int2 ev = csr[idx];
            off_n = ev.x;
            ab_n = (unsigned)ev.y;
        }
    }
    for (int g = 0; g < Gmax; g++) {
        int off = off_n;
        unsigned ab = ab_n;
        off_n = 0;
        ab_n = 0;
        int idx2 = s + (g + 1) * 8 + l8;
        if (idx2 < e) {
            int2 ev = csr[idx2];
            off_n = ev.x;
            ab_n = (unsigned)ev.y;
        }
        int n = e - s - g * 8;
        n = max(0, min(8, n));
        int nr = __reduce_max_sync(0xffffffffu, (n + 3) & ~3);   // pad to 4 (a=0 lanes noop)
        __half2 h0 = hz, h1 = hz, h2 = hz, h3 = hz;
        for (int j = 0; j < nr; j += 4) {
            int o0 = __shfl_sync(~0u, off, j + 0, 8), o1 = __shfl_sync(~0u, off, j + 1, 8);
            int o2 = __shfl_sync(~0u, off, j + 2, 8), o3 = __shfl_sync(~0u, off, j + 3, 8);
            unsigned b0 = __shfl_sync(~0u, ab, j + 0, 8), b1 = __shfl_sync(~0u, ab, j + 1, 8);
            unsigned b2 = __shfl_sync(~0u, ab, j + 2, 8), b3 = __shfl_sync(~0u, ab, j + 3, 8);
            uint4 r0 = *(const uint4*)(Xb + o0 + loff);
            uint4 r1 = *(const uint4*)(Xb + o1 + loff);
            uint4 r2 = *(const uint4*)(Xb + o2 + loff);
            uint4 r3 = *(const uint4*)(Xb + o3 + loff);
            h0 = __hfma2(u2h(b0), u2h(r0.x), h0);
            h1 = __hfma2(u2h(b0), u2h(r0.y), h1);
            h2 = __hfma2(u2h(b0), u2h(r0.z), h2);
            h3 = __hfma2(u2h(b0), u2h(r0.w), h3);
            h0 = __hfma2(u2h(b1), u2h(r1.x), h0);
            h1 = __hfma2(u2h(b1), u2h(r1.y), h1);
            h2 = __hfma2(u2h(b1), u2h(r1.z), h2);
            h3 = __hfma2(u2h(b1), u2h(r1.w), h3);
            h0 = __hfma2(u2h(b2), u2h(r2.x), h0);
            h1 = __hfma2(u2h(b2), u2h(r2.y), h1);
            h2 = __hfma2(u2h(b2), u2h(r2.z), h2);
            h3 = __hfma2(u2h(b2), u2h(r2.w), h3);
            h0 = __hfma2(u2h(b3), u2h(r3.x), h0);
            h1 = __hfma2(u2h(b3), u2h(r3.y), h1);
            h2 = __hfma2(u2h(b3), u2h(r3.z), h2);
            h3 = __hfma2(u2h(b3), u2h(r3.w), h3);
        }
        float2 f;
        f = __half22float2(h0); ac0 += f.x; ac1 += f.y;
        f = __half22float2(h1); ac2 += f.x; ac3 += f.y;
        f = __half22float2(h2); ac4 += f.x; ac5 += f.y;
        f = __half22float2(h3); ac6 += f.x; ac7 += f.y;
    }
    if (iskg) {
        float sc = (e > s) ? 1.f / d_rowsum[row] : 0.f;   // fold softmax normalization
        ac0 *= sc; ac1 *= sc; ac2 *= sc; ac3 *= sc;
        ac4 *= sc; ac5 *= sc; ac6 *= sc; ac7 *= sc;
        uint4 o;
        o.x = h2u(__floats2half2_rn(ac0, ac1));
        o.y = h2u(__floats2half2_rn(ac2, ac3));
        o.z = h2u(__floats2half2_rn(ac4, ac5));
        o.w = h2u(__floats2half2_rn(ac6, ac7));
        *(uint4*)((char*)d_kg16[cur ^ 1] + (size_t)row * 128 + loff) = o;
    } else {
        *(float4*)(d_ig + (size_t)row * 64 + l8 * 8) = make_float4(ac0, ac1, ac2, ac3);
        *(float4*)(d_ig + (size_t)row * 64 + l8 * 8 + 4) = make_float4(ac4, ac5, ac6, ac7);
    }
}

// ===== Launches 5,7,9: fusion gate via mma.sync (HMMA) + f16x2-tanh sigmoid + users =====
// S = [KG | IG](64x128 fp16) @ [Wa; Wb](128x64 fp16), fp32 accum.
__global__ void __launch_bounds__(256) k_fusion_users(int cur) {
    if (blockIdx.x >= NBF) {
        int i = (blockIdx.x - NBF) * 256 + threadIdx.x;
        if (i >= N_USR * 16) return;
        const float4* src = (const float4*)(d_ig + (size_t)N_ENT * 64);
        float4 v = src[i];
        ((uint2*)(d_xy16[cur ^ 1] + (size_t)N_ENT * 32))[i] = pack_h4(v.x, v.y, v.z, v.w);
        float4* as = (float4*)(d_sum + (size_t)N_ENT * 64);
        float4 a = as[i];
        a.x += v.x; a.y += v.y; a.z += v.z; a.w += v.w;
        as[i] = a;
        return;
    }
    // A tile: 64 rows x 136 halfs (cols 0-63 = KG, 64-127 = IG; 8 halfs pad)
    // W tile: 128 rows x 72 halfs (64 cols + 8 pad)
    __shared__ __align__(16) char sAb[64 * 136 * 2];
    __shared__ __align__(16) char sWb[128 * 72 * 2];
    const char* __restrict__ KG16 = (const char*)d_kg16[cur ^ 1];
    const float* __restrict__ IG = d_ig;
    int row0 = blockIdx.x * 64;
    int tid = threadIdx.x;  // 256
    // stage KG (fp16, 64x64): 512 uint4
    for (int i = tid; i < 512; i += 256) {
        int rr = i >> 3, c8 = (i & 7) * 8;
        int gr = row0 + rr;
        uint4 v = make_uint4(0u, 0u, 0u, 0u);
        if (gr < N_ENT) v = *(const uint4*)(KG16 + (size_t)gr * 128 + c8 * 2);
        *(uint4*)(sAb + (rr * 136 + c8) * 2) = v;
    }
    // stage IG (fp32 -> fp16, 64x64): 1024 float4 -> uint2
    for (int i = tid; i < 1024; i += 256) {
        int rr = i >> 4, c4 = (i & 15) * 4;
        int gr = row0 + rr;
        uint2 u = make_uint2(0u, 0u);
        if (gr < N_ENT) {
            float4 v = *(const float4*)(IG + (size_t)gr * 64 + c4);
            u = pack_h4(v.x, v.y, v.z, v.w);
        }
        *(uint2*)(sAb + (rr * 136 + 64 + c4) * 2) = u;
    }
    // stage W (fp16, 128x64): 1024 uint4
    for (int i = tid; i < 1024; i += 256) {
        int k = i >> 3, c8 = (i & 7) * 8;
        uint4 v = *(const uint4*)((const char*)d_w16 + (k * 64 + c8) * 2);
        *(uint4*)(sWb + (k * 72 + c8) * 2) = v;
    }
    __syncthreads();

    int wid = tid >> 5, lane = tid & 31;
    int r = wid >> 1;          // 0..3: 16-row slab
    int c = wid & 1;           // 0..1: 32-col slab
    float acc[4][4];
    #pragma unroll
    for (int nb = 0; nb < 4; nb++)
        #pragma unroll
        for (int q = 0; q < 4; q++) acc[nb][q] = 0.f;
    unsigned sA_u = (unsigned)__cvta_generic_to_shared(sAb);
    unsigned sW_u = (unsigned)__cvta_generic_to_shared(sWb);
    // A ldmatrix addresses: lane 0-15 -> rows 0-15 (k lo 8), 16-31 -> rows 0-15 (k hi 8)
    unsigned aBase = sA_u + ((r * 16 + (lane & 15)) * 136 + ((lane >> 4) << 3)) * 2;
    unsigned bRowBase = sW_u + ((lane & 15) * 72 + c * 32) * 2;
    #pragma unroll
    for (int kk = 0; kk < 8; kk++) {
        unsigned a0, a1, a2, a3;
        ldsm_x4(a0, a1, a2, a3, aBase + kk * 32);            // +16 halfs per k-step
        unsigned bk = bRowBase + kk * 16 * 72 * 2;           // +16 W-rows per k-step
        #pragma unroll
        for (int nb = 0; nb < 4; nb++) {
            unsigned b0, b1;
            ldsm_x2t(b0, b1, bk + nb * 16);                  // +8 cols
            mma16816(acc[nb], a0, a1, a2, a3, b0, b1);
        }
    }
    // epilogue: c-frag (q0,q1)=(row g, cols 2t,2t+1), (q2,q3)=(row g+8)
    int g = lane >> 2, tg = lane & 3;
    int lr0 = r * 16 + g;
    #pragma unroll
    for (int nb = 0; nb < 4; nb++) {
        int col = c * 32 + nb * 8 + tg * 2;
        #pragma unroll
        for (int p = 0; p < 2; p++) {
            int lr = lr0 + p * 8;
            int gr = row0 + lr;
            if (gr < N_ENT) {
                float s0 = acc[nb][2 * p], s1 = acc[nb][2 * p + 1];
                float2 kg = __half22float2(*(const __half2*)(sAb + (lr * 136 + col) * 2));
                float2 ig = *(const float2*)(IG + (size_t)gr * 64 + col);
                float2 t = tanh2(0.5f * s0, 0.5f * s1);
                float ox = fmaf(t.x, 0.5f * (kg.x - ig.x), 0.5f * (kg.x + ig.x));
                float oy = fmaf(t.y, 0.5f * (kg.y - ig.y), 0.5f * (kg.y + ig.y));
                *(__half2*)((char*)d_xy16[cur ^ 1] + (size_t)gr * 128 + col * 2) =
                    __floats2half2_rn(ox, oy);
                float2* sp = (float2*)(d_sum + (size_t)gr * 64 + col);
                float2 sv = *sp;
                sv.x += ig.x;
                sv.y += ig.y;
                *sp = sv;
            }
        }
    }
}

// ====== Launch 10: final score GEMM + re-zero counters for the next graph replay ==========
__global__ void k_final(const int* __restrict__ uids, const int* __restrict__ iids,
                        float* __restrict__ out) {
    int bid = blockIdx.x;
    int tx = threadIdx.x, ty = threadIdx.y;
    if (bid >= 8192) {
        int t = ty * 16 + tx;
        int i = (bid - 8192) * 256 + t;
        if (i < N_ENT) d_kg_cnt[i] = 0;
        else {
            i -= N_ENT;
            if (i < N_TOT) d_ain_cnt[i] = 0;
        }
        return;
    }
    __shared__ float sU[16][68];
    __shared__ float sI[16][68];
    int ix = bid & 127, iy = bid >> 7;
    int u0 = iy * 16, i0 = ix * 16;
    {
        int ur = uids[u0 + ty];
        *(float4*)&sU[ty][tx * 4] = *(const float4*)(d_sum + (size_t)ur * 64 + tx * 4);
        int ir = iids[i0 + ty];
        *(float4*)&sI[ty][tx * 4] = *(const float4*)(d_sum + (size_t)ir * 64 + tx * 4);
    }
    __syncthreads();
    float acc = 0.f;
    #pragma unroll
    for (int k = 0; k < 64; k++) acc += sU[ty][k] * sI[tx][k];
    out[(size_t)(u0 + ty) * 2048 + i0 + tx] = acc;
}

// ---------------- launch ----------------
extern "C" void kernel_launch(void* const* d_in, const int* in_sizes, int n_in,
                              void* d_out, int out_size) {
    const float* E0   = (const float*)d_in[0];
    const float* rel  = (const float*)d_in[1];
    const float* Wk   = (const float*)d_in[2];
    const float* Wkb  = (const float*)d_in[3];
    const float* Wa   = (const float*)d_in[4];
    const float* Wb   = (const float*)d_in[5];
    const int*   kg_h = (const int*)d_in[6];
    const int*   kg_t = (const int*)d_in[7];
    const int*   kg_r = (const int*)d_in[8];
    const int*   a_r  = (const int*)d_in[9];
    const int*   a_c  = (const int*)d_in[10];
    const float* a_v  = (const float*)d_in[11];
    const int*   uids = (const int*)d_in[12];
    const int*   iids = (const int*)d_in[13];
    float* out = (float*)d_out;

    // 0: hist   1: init+PQ+W16+zero   2: atbt+scan   3: scatter (capture slot)
    k_hist<<<B_H, 256>>>(kg_h, a_r);
    k_setup2<<<B_I + B_P + B_W + B_Z, 256>>>(E0, Wk, Wkb, rel, Wa, Wb);
    k_atbt_scan<<<B_ATBT + NB_KG + NB_AIN, 1024>>>(E0);
    k_scatter<<<B_H, 256>>>(kg_h, kg_t, kg_r, a_r, a_c, a_v);

    int cur = 0;
    for (int l = 0; l < 3; l++) {
        k_spmm<<<7813, 256>>>(cur);
        k_fusion_users<<<NBF + (N_USR * 16 + 255) / 256, 256>>>(cur);
        cur ^= 1;
    }

    dim3 fb(16, 16);
    k_final<<<8192 + 977, fb>>>(uids, iids, out);
    (void)in_sizes; (void)n_in; (void)out_size;
}